// round 5
// baseline (speedup 1.0000x reference)
#include <cuda_runtime.h>
#include <cuda_bf16.h>

#define NN 50000
#define NE 800000
#define NIDX 25000

typedef unsigned long long ull;

// ---------------- scratch (__device__ globals, zero at load) ----------------
// Invariant at START of every call: g_hist == 0 (re-zeroed by scan_blocks).
__device__ int    g_hist  [NN];
__device__ int    g_rowoff[NN + 1];
__device__ int    g_cursor[NN];
__device__ int    g_blocksum[64];
__device__ int    g_srcS  [NE];       // src node id, dst-sorted
__device__ float4 g_pseudoS[NE];      // pseudo, dst-sorted
__device__ float  g_h1[NN * 16];
__device__ float  g_h2[NN * 16];

// ---- packed f32x2 helpers -------------------------------------------------
__device__ __forceinline__ ull ffma2(ull a, ull b, ull c) {
    ull d;
    asm("fma.rn.f32x2 %0, %1, %2, %3;" : "=l"(d) : "l"(a), "l"(b), "l"(c));
    return d;
}
__device__ __forceinline__ ull pack2(float lo, float hi) {
    ull r;
    asm("mov.b64 %0, {%1, %2};" : "=l"(r) : "f"(lo), "f"(hi));
    return r;
}
__device__ __forceinline__ void unpack2(ull v, float& lo, float& hi) {
    asm("mov.b64 {%0, %1}, %2;" : "=f"(lo), "=f"(hi) : "l"(v));
}
__device__ __forceinline__ ull relu2(ull v) {
    float lo, hi;
    unpack2(v, lo, hi);
    lo = fmaxf(lo, 0.0f);
    hi = fmaxf(hi, 0.0f);
    return pack2(lo, hi);
}

// Per-lane partial for one edge: 4 ci-pairs (xv = 8 source floats as 4 f32x2).
__device__ __forceinline__ float edge_comp(float4 ps,
                                           ulonglong2 v0, ulonglong2 v1,
                                           const ull* Px, const ull* Py,
                                           const ull* Pz, const ull* Pc)
{
    ull p0 = pack2(ps.x, ps.x), p1 = pack2(ps.y, ps.y), p2 = pack2(ps.z, ps.z);
    ull xv[4] = { v0.x, v0.y, v1.x, v1.y };
    ull acc = 0;
#pragma unroll
    for (int q = 0; q < 4; q++) {
        ull w = ffma2(p2, Pz[q], Pc[q]);
        w = ffma2(p1, Py[q], w);
        w = ffma2(p0, Px[q], w);
        w = relu2(w);
        acc = ffma2(xv[q], w, acc);
    }
    float lo, hi;
    unpack2(acc, lo, hi);
    return lo + hi;
}

// Fold edge-MLP params into smem (packed over ci-pairs).
// As floats: sf[((k*4+c)*16+co)*2 + (ci&1)], k = ci>>1, c in {Wx,Wy,Wz,const}.
__device__ __forceinline__ void fold_smem_nosync(float* sf,
                                                 const float* __restrict__ lw,
                                                 const float* __restrict__ lb,
                                                 const float* __restrict__ ga,
                                                 const float* __restrict__ be, int D)
{
    for (int j = threadIdx.x; j < D; j += blockDim.x) {
        float g = ga[j];
        float c0 = lw[j] * g;
        float c1 = lw[D + j] * g;
        float c2 = lw[2 * D + j] * g;
        float c3 = fmaf(lb[j], g, be[j]);
        int ci = j >> 4, co = j & 15;
        int k = ci >> 1, h = ci & 1;
        sf[((k * 4 + 0) * 16 + co) * 2 + h] = c0;
        sf[((k * 4 + 1) * 16 + co) * 2 + h] = c1;
        sf[((k * 4 + 2) * 16 + co) * 2 + h] = c2;
        sf[((k * 4 + 3) * 16 + co) * 2 + h] = c3;
    }
}

// ---------------------------- CSR construction -----------------------------
__global__ void hist_kernel(const int* __restrict__ ei) {
    int e = blockIdx.x * blockDim.x + threadIdx.x;
    if (e < NE) atomicAdd(&g_hist[ei[NE + e]], 1);
}

// 49 blocks x 1024: block-local exclusive scan of hist -> rowoff(local),
// block totals -> blocksum. Also re-zeroes hist for the next call.
__global__ void scan_blocks_kernel() {
    int tid = threadIdx.x;
    int n = blockIdx.x * 1024 + tid;
    int lane = tid & 31, wid = tid >> 5;
    int v = (n < NN) ? g_hist[n] : 0;
    if (n < NN) g_hist[n] = 0;

    int x = v;
#pragma unroll
    for (int d = 1; d < 32; d <<= 1) {
        int y = __shfl_up_sync(0xffffffffu, x, d);
        if (lane >= d) x += y;
    }
    __shared__ int wsum[32];
    if (lane == 31) wsum[wid] = x;
    __syncthreads();
    if (wid == 0) {
        int w = wsum[lane];
#pragma unroll
        for (int d = 1; d < 32; d <<= 1) {
            int y = __shfl_up_sync(0xffffffffu, w, d);
            if (lane >= d) w += y;
        }
        wsum[lane] = w;
    }
    __syncthreads();
    int incl = x + (wid > 0 ? wsum[wid - 1] : 0);
    if (n < NN) g_rowoff[n] = incl - v;     // local exclusive
    if (tid == 1023) g_blocksum[blockIdx.x] = incl;
}

// 64 threads: exclusive scan of 49 block sums (in place).
__global__ void scan_tops_kernel() {
    int t = threadIdx.x;
    int lane = t & 31, wid = t >> 5;
    int v = (t < 49) ? g_blocksum[t] : 0;
    int x = v;
#pragma unroll
    for (int d = 1; d < 32; d <<= 1) {
        int y = __shfl_up_sync(0xffffffffu, x, d);
        if (lane >= d) x += y;
    }
    __shared__ int ws[2];
    if (lane == 31) ws[wid] = x;
    __syncthreads();
    if (wid == 1) x += ws[0];
    if (t < 49) g_blocksum[t] = x - v;      // exclusive
}

// Globalize offsets, init cursors, cap rowoff[NN].
__global__ void fix_offsets_kernel() {
    int n = blockIdx.x * blockDim.x + threadIdx.x;
    if (n < NN) {
        int off = g_rowoff[n] + g_blocksum[n >> 10];
        g_rowoff[n] = off;
        g_cursor[n] = off;
    }
    if (n == 0) g_rowoff[NN] = NE;
}

// Scatter edges into dst-sorted order; compute pseudo here.
__global__ void scatter_kernel(const int* __restrict__ ei, const float* __restrict__ pos) {
    int e = blockIdx.x * blockDim.x + threadIdx.x;
    if (e >= NE) return;
    int s = ei[e];
    int d = ei[NE + e];
    float4 ps;
    ps.x = __ldg(&pos[d * 3 + 0]) - __ldg(&pos[s * 3 + 0]);
    ps.y = __ldg(&pos[d * 3 + 1]) - __ldg(&pos[s * 3 + 1]);
    ps.z = __ldg(&pos[d * 3 + 2]) - __ldg(&pos[s * 3 + 2]);
    ps.w = 0.0f;
    int p = atomicAdd(&g_cursor[d], 1);
    g_srcS[p] = s;
    g_pseudoS[p] = ps;
}

// ------------------------- fused layer kernels -----------------------------
// CI=16: warp per node. half = ci-half, co = lane&15. No atomics.
__global__ void __launch_bounds__(256)
layer16_kernel(const float* __restrict__ hin,   // [NN,16]
               const float* __restrict__ lw, const float* __restrict__ lb,
               const float* __restrict__ ga, const float* __restrict__ be,
               const float* __restrict__ root,  // [16,16]
               const float* __restrict__ bias,  // [16]
               float* __restrict__ hout)        // [NN,16]
{
    __shared__ ull   sP[8 * 4 * 16];
    __shared__ float sR[256];
    __shared__ float sB[16];
    fold_smem_nosync((float*)sP, lw, lb, ga, be, 256);
    for (int j = threadIdx.x; j < 256; j += 256) sR[j] = root[j];
    if (threadIdx.x < 16) sB[threadIdx.x] = bias[threadIdx.x];
    __syncthreads();

    int lane = threadIdx.x & 31;
    int co = lane & 15, half = lane >> 4;

    ull Px[4], Py[4], Pz[4], Pc[4];
#pragma unroll
    for (int k = 0; k < 4; k++) {
        int kg = half * 4 + k;
        Px[k] = sP[(kg * 4 + 0) * 16 + co];
        Py[k] = sP[(kg * 4 + 1) * 16 + co];
        Pz[k] = sP[(kg * 4 + 2) * 16 + co];
        Pc[k] = sP[(kg * 4 + 3) * 16 + co];
    }

    int w  = (blockIdx.x * 256 + threadIdx.x) >> 5;
    int nw = (gridDim.x * 256) >> 5;

    for (int n = w; n < NN; n += nw) {
        int r0 = __ldg(&g_rowoff[n]);
        int r1 = __ldg(&g_rowoff[n + 1]);
        float acc = 0.0f;

        for (int base = r0; base < r1; base += 32) {
            int cnt = min(32, r1 - base);
            int mySrc = (lane < cnt) ? __ldg(&g_srcS[base + lane]) : 0;
            int j = 0;
            for (; j + 2 <= cnt; j += 2) {
                int sA = __shfl_sync(0xffffffffu, mySrc, j);
                int sBv = __shfl_sync(0xffffffffu, mySrc, j + 1);
                float4 pA = __ldg(&g_pseudoS[base + j]);
                float4 pB = __ldg(&g_pseudoS[base + j + 1]);
                const ulonglong2* xa = (const ulonglong2*)(hin + (size_t)sA * 16) + half * 2;
                const ulonglong2* xb = (const ulonglong2*)(hin + (size_t)sBv * 16) + half * 2;
                ulonglong2 va0 = __ldg(&xa[0]), va1 = __ldg(&xa[1]);
                ulonglong2 vb0 = __ldg(&xb[0]), vb1 = __ldg(&xb[1]);
                acc += edge_comp(pA, va0, va1, Px, Py, Pz, Pc);
                acc += edge_comp(pB, vb0, vb1, Px, Py, Pz, Pc);
            }
            if (j < cnt) {
                int sA = __shfl_sync(0xffffffffu, mySrc, j);
                float4 pA = __ldg(&g_pseudoS[base + j]);
                const ulonglong2* xa = (const ulonglong2*)(hin + (size_t)sA * 16) + half * 2;
                ulonglong2 va0 = __ldg(&xa[0]), va1 = __ldg(&xa[1]);
                acc += edge_comp(pA, va0, va1, Px, Py, Pz, Pc);
            }
        }
        acc += __shfl_xor_sync(0xffffffffu, acc, 16);

        // node update
        float inv = 1.0f / fmaxf((float)(r1 - r0), 1.0f);
        float res = fmaf(acc, inv, sB[co]);
        float myh = __ldg(&hin[(size_t)n * 16 + co]);   // lane ci (0..15) holds h[n,ci]
#pragma unroll
        for (int ci = 0; ci < 16; ci++) {
            float hv = __shfl_sync(0xffffffffu, myh, ci);
            res = fmaf(hv, sR[ci * 16 + co], res);
        }
        if (lane < 16) hout[(size_t)n * 16 + co] = fmaxf(res, 0.0f);
    }
}

// CI=8: HALF-warp per node (16 lanes cover co; each lane covers all 8 ci).
__global__ void __launch_bounds__(256)
layer8_kernel(const float* __restrict__ hin,    // [NN,8]
              const float* __restrict__ lw, const float* __restrict__ lb,
              const float* __restrict__ ga, const float* __restrict__ be,
              const float* __restrict__ root,   // [8,16]
              const float* __restrict__ bias,   // [16]
              float* __restrict__ hout)         // [NN,16]
{
    __shared__ ull   sP[4 * 4 * 16];
    __shared__ float sR[128];
    __shared__ float sB[16];
    fold_smem_nosync((float*)sP, lw, lb, ga, be, 128);
    for (int j = threadIdx.x; j < 128; j += 256) sR[j] = root[j];
    if (threadIdx.x < 16) sB[threadIdx.x] = bias[threadIdx.x];
    __syncthreads();

    int co = threadIdx.x & 15;

    ull Px[4], Py[4], Pz[4], Pc[4];
#pragma unroll
    for (int k = 0; k < 4; k++) {
        Px[k] = sP[(k * 4 + 0) * 16 + co];
        Py[k] = sP[(k * 4 + 1) * 16 + co];
        Pz[k] = sP[(k * 4 + 2) * 16 + co];
        Pc[k] = sP[(k * 4 + 3) * 16 + co];
    }

    int slot   = (blockIdx.x * 256 + threadIdx.x) >> 4;
    int nslots = (gridDim.x * 256) >> 4;

    for (int n = slot; n < NN; n += nslots) {
        int r0 = __ldg(&g_rowoff[n]);
        int r1 = __ldg(&g_rowoff[n + 1]);
        float acc = 0.0f;

        for (int base = r0; base < r1; base += 16) {
            int cnt = min(16, r1 - base);
            int mySrc = (co < cnt) ? __ldg(&g_srcS[base + co]) : 0;
            int j = 0;
            for (; j + 2 <= cnt; j += 2) {
                int sA = __shfl_sync(0xffffffffu, mySrc, j, 16);
                int sBv = __shfl_sync(0xffffffffu, mySrc, j + 1, 16);
                float4 pA = __ldg(&g_pseudoS[base + j]);
                float4 pB = __ldg(&g_pseudoS[base + j + 1]);
                const ulonglong2* xa = (const ulonglong2*)(hin + (size_t)sA * 8);
                const ulonglong2* xb = (const ulonglong2*)(hin + (size_t)sBv * 8);
                ulonglong2 va0 = __ldg(&xa[0]), va1 = __ldg(&xa[1]);
                ulonglong2 vb0 = __ldg(&xb[0]), vb1 = __ldg(&xb[1]);
                acc += edge_comp(pA, va0, va1, Px, Py, Pz, Pc);
                acc += edge_comp(pB, vb0, vb1, Px, Py, Pz, Pc);
            }
            if (j < cnt) {
                int sA = __shfl_sync(0xffffffffu, mySrc, j, 16);
                float4 pA = __ldg(&g_pseudoS[base + j]);
                const ulonglong2* xa = (const ulonglong2*)(hin + (size_t)sA * 8);
                ulonglong2 va0 = __ldg(&xa[0]), va1 = __ldg(&xa[1]);
                acc += edge_comp(pA, va0, va1, Px, Py, Pz, Pc);
            }
        }

        float inv = 1.0f / fmaxf((float)(r1 - r0), 1.0f);
        float res = fmaf(acc, inv, sB[co]);
        float myh = (co < 8) ? __ldg(&hin[(size_t)n * 8 + co]) : 0.0f;
#pragma unroll
        for (int ci = 0; ci < 8; ci++) {
            float hv = __shfl_sync(0xffffffffu, myh, ci, 16);
            res = fmaf(hv, sR[ci * 16 + co], res);
        }
        hout[(size_t)n * 16 + co] = fmaxf(res, 0.0f);
    }
}

// ---------------------------------------------------------------------------
__global__ void gather_kernel(const float* __restrict__ h,
                              const float* __restrict__ pos,
                              const int*   __restrict__ batch,
                              const int*   __restrict__ idx,
                              float* __restrict__ out)
{
    int i = blockIdx.x * blockDim.x + threadIdx.x;
    if (i >= NIDX) return;
    int n = idx[i];
    float4* od = (float4*)(out + (size_t)i * 16);
    const float4* hs = (const float4*)(h + (size_t)n * 16);
#pragma unroll
    for (int q = 0; q < 4; q++) od[q] = hs[q];
    out[NIDX * 16 + i * 3 + 0] = pos[n * 3 + 0];
    out[NIDX * 16 + i * 3 + 1] = pos[n * 3 + 1];
    out[NIDX * 16 + i * 3 + 2] = pos[n * 3 + 2];
    reinterpret_cast<int*>(out)[NIDX * 19 + i] = batch[n];
}

// ---------------------------------------------------------------------------
extern "C" void kernel_launch(void* const* d_in, const int* in_sizes, int n_in,
                              void* d_out, int out_size)
{
    const float* x   = (const float*)d_in[0];
    const float* pos = (const float*)d_in[1];
    const float* lw0 = (const float*)d_in[2],  *lb0 = (const float*)d_in[3],
               * g0  = (const float*)d_in[4],  *be0 = (const float*)d_in[5],
               * r0  = (const float*)d_in[6],  *bi0 = (const float*)d_in[7];
    const float* lw1 = (const float*)d_in[8],  *lb1 = (const float*)d_in[9],
               * g1  = (const float*)d_in[10], *be1 = (const float*)d_in[11],
               * r1  = (const float*)d_in[12], *bi1 = (const float*)d_in[13];
    const float* lw2 = (const float*)d_in[14], *lb2 = (const float*)d_in[15],
               * g2  = (const float*)d_in[16], *be2 = (const float*)d_in[17],
               * r2  = (const float*)d_in[18], *bi2 = (const float*)d_in[19];
    const int* batch = (const int*)d_in[20];
    const int* idx   = (const int*)d_in[21];
    const int* ei    = (const int*)d_in[22];
    float* out = (float*)d_out;

    float *h1, *h2;
    cudaGetSymbolAddress((void**)&h1, g_h1);
    cudaGetSymbolAddress((void**)&h2, g_h2);

    dim3 egrid((NE + 255) / 256);

    // CSR build (per call; deterministic sets, arbitrary within-row order)
    hist_kernel<<<egrid, 256>>>(ei);
    scan_blocks_kernel<<<49, 1024>>>();
    scan_tops_kernel<<<1, 64>>>();
    fix_offsets_kernel<<<196, 256>>>();
    scatter_kernel<<<egrid, 256>>>(ei, pos);

    // Fused layers (no atomics)
    layer8_kernel <<<1250, 256>>>(x,  lw0, lb0, g0, be0, r0, bi0, h1);
    layer16_kernel<<<1250, 256>>>(h1, lw1, lb1, g1, be1, r1, bi1, h2);
    layer16_kernel<<<1250, 256>>>(h2, lw2, lb2, g2, be2, r2, bi2, h1);

    gather_kernel<<<(NIDX + 255) / 256, 256>>>(h1, pos, batch, idx, out);
}

// round 6
// speedup vs baseline: 1.0235x; 1.0235x over previous
#include <cuda_runtime.h>
#include <cuda_bf16.h>

#define NN 50000
#define NE 800000
#define NIDX 25000

#define EB 592                      // edge blocks = exactly 1 wave at 4 blocks/SM
#define NSL8  ((EB * 256) >> 4)     // 9472 half-warp slots (edge8)
#define NW16  ((EB * 256) >> 5)     // 4736 warps (edge16)
#define ITER8  ((NE + 2 * NSL8 - 1) / (2 * NSL8))   // 43
#define ITER16 ((NE + 2 * NW16 - 1) / (2 * NW16))   // 85

typedef unsigned long long ull;

// Scratch (__device__ globals; zero-initialized at load).
// Invariants at START of every call: g_deg == 0, g_aggr == 0 (re-zeroed by node kernels).
__device__ float  g_deg [NN];
__device__ float  g_aggr[NN * 16];
__device__ float  g_h1  [NN * 16];
__device__ float  g_h2  [NN * 16];
__device__ float4 g_pseudo[NE];
__device__ int    g_dummy;

// ---- packed f32x2 helpers -------------------------------------------------
__device__ __forceinline__ ull ffma2(ull a, ull b, ull c) {
    ull d;
    asm("fma.rn.f32x2 %0, %1, %2, %3;" : "=l"(d) : "l"(a), "l"(b), "l"(c));
    return d;
}
__device__ __forceinline__ ull pack2(float lo, float hi) {
    ull r;
    asm("mov.b64 %0, {%1, %2};" : "=l"(r) : "f"(lo), "f"(hi));
    return r;
}
__device__ __forceinline__ void unpack2(ull v, float& lo, float& hi) {
    asm("mov.b64 {%0, %1}, %2;" : "=f"(lo), "=f"(hi) : "l"(v));
}
__device__ __forceinline__ ull relu2(ull v) {
    float lo, hi;
    unpack2(v, lo, hi);
    lo = fmaxf(lo, 0.0f);
    hi = fmaxf(hi, 0.0f);
    return pack2(lo, hi);
}
__device__ __forceinline__ void red_v4(float* p, float a, float b, float c, float d) {
    asm volatile("red.global.add.v4.f32 [%0], {%1, %2, %3, %4};"
                 :: "l"(p), "f"(a), "f"(b), "f"(c), "f"(d) : "memory");
}

// Collect co-quads, one red.v4 per 4 lanes. ALL 32 lanes must reach this.
__device__ __forceinline__ void quad_red(float sum, int co, bool active, float* addr) {
    float b  = __shfl_xor_sync(0xffffffffu, sum, 1);
    float v0 = (co & 1) ? b : sum;
    float v1 = (co & 1) ? sum : b;
    float c0 = __shfl_xor_sync(0xffffffffu, v0, 2);
    float c1 = __shfl_xor_sync(0xffffffffu, v1, 2);
    if (active && (co & 3) == 0) red_v4(addr, v0, v1, c0, c1);
}

// Per-lane partial for one edge: 4 ci-pairs.
__device__ __forceinline__ float edge_comp(float px, float py, float pz,
                                           ulonglong2 v0, ulonglong2 v1,
                                           const ull* Px, const ull* Py,
                                           const ull* Pz, const ull* Pc)
{
    ull p0 = pack2(px, px), p1 = pack2(py, py), p2 = pack2(pz, pz);
    ull xv[4] = { v0.x, v0.y, v1.x, v1.y };
    ull acc = 0;
#pragma unroll
    for (int q = 0; q < 4; q++) {
        ull w = ffma2(p2, Pz[q], Pc[q]);
        w = ffma2(p1, Py[q], w);
        w = ffma2(p0, Px[q], w);
        w = relu2(w);
        acc = ffma2(xv[q], w, acc);
    }
    float lo, hi;
    unpack2(acc, lo, hi);
    return lo + hi;
}

// Fold edge-MLP params into smem (packed over ci-pairs).
__device__ __forceinline__ void fold_smem(float* sf,
                                          const float* __restrict__ lw,
                                          const float* __restrict__ lb,
                                          const float* __restrict__ ga,
                                          const float* __restrict__ be, int D)
{
    for (int j = threadIdx.x; j < D; j += blockDim.x) {
        float g = ga[j];
        float c0 = lw[j] * g;
        float c1 = lw[D + j] * g;
        float c2 = lw[2 * D + j] * g;
        float c3 = fmaf(lb[j], g, be[j]);
        int ci = j >> 4, co = j & 15;
        int k = ci >> 1, h = ci & 1;
        sf[((k * 4 + 0) * 16 + co) * 2 + h] = c0;
        sf[((k * 4 + 1) * 16 + co) * 2 + h] = c1;
        sf[((k * 4 + 2) * 16 + co) * 2 + h] = c2;
        sf[((k * 4 + 3) * 16 + co) * 2 + h] = c3;
    }
    __syncthreads();
}

// Profiler-alignment / warmup no-op (shifts ncu capture onto edge16).
__global__ void align_kernel() { if (threadIdx.x == 0) g_dummy = 0; }

// ---------------------------------------------------------------------------
// Layer-0 edge kernel (CI=8): half-warp per edge. Persistent, uniform ITER8
// iterations (shfl-converged tails). Also computes pseudo + degree.
__global__ void __launch_bounds__(256, 4)
edge8_kernel(const float* __restrict__ x,     // [NN, 8]
             const float* __restrict__ pos,   // [NN, 3]
             const int*   __restrict__ ei,    // [2, NE]
             const float* __restrict__ lw, const float* __restrict__ lb,
             const float* __restrict__ ga, const float* __restrict__ be,
             float* __restrict__ aggr)        // [NN, 16]
{
    __shared__ ull sP[4 * 4 * 16];
    fold_smem((float*)sP, lw, lb, ga, be, 128);

    int co = threadIdx.x & 15;
    ull Px[4], Py[4], Pz[4], Pc[4];
#pragma unroll
    for (int k = 0; k < 4; k++) {
        Px[k] = sP[(k * 4 + 0) * 16 + co];
        Py[k] = sP[(k * 4 + 1) * 16 + co];
        Pz[k] = sP[(k * 4 + 2) * 16 + co];
        Pc[k] = sP[(k * 4 + 3) * 16 + co];
    }

    int slot = (blockIdx.x * 256 + threadIdx.x) >> 4;   // 0..NSL8-1

    // prefetch iteration 0 indices (clamped)
    int eA = slot, eB = slot + NSL8;
    int sA = __ldg(&ei[eA]), dA = __ldg(&ei[NE + eA]);
    int sB = __ldg(&ei[eB]), dB = __ldg(&ei[NE + eB]);

    for (int k = 0; k < ITER8; k++) {
        int ceA = slot + k * 2 * NSL8;
        int ceB = ceA + NSL8;
        bool vA = (ceA < NE), vB = (ceB < NE);

        // dependent loads for current pair
        float ax = __ldg(&pos[dA * 3 + 0]) - __ldg(&pos[sA * 3 + 0]);
        float ay = __ldg(&pos[dA * 3 + 1]) - __ldg(&pos[sA * 3 + 1]);
        float az = __ldg(&pos[dA * 3 + 2]) - __ldg(&pos[sA * 3 + 2]);
        float bx = __ldg(&pos[dB * 3 + 0]) - __ldg(&pos[sB * 3 + 0]);
        float by = __ldg(&pos[dB * 3 + 1]) - __ldg(&pos[sB * 3 + 1]);
        float bz = __ldg(&pos[dB * 3 + 2]) - __ldg(&pos[sB * 3 + 2]);
        const ulonglong2* xrA = (const ulonglong2*)(x + (size_t)sA * 8);
        const ulonglong2* xrB = (const ulonglong2*)(x + (size_t)sB * 8);
        ulonglong2 vA0 = __ldg(&xrA[0]), vA1 = __ldg(&xrA[1]);
        ulonglong2 vB0 = __ldg(&xrB[0]), vB1 = __ldg(&xrB[1]);

        int cdA = dA, cdB = dB;

        // prefetch next pair (clamped to stay in-bounds)
        if (k + 1 < ITER8) {
            int nA = ceA + 2 * NSL8; if (nA >= NE) nA = 0;
            int nB = nA + NSL8;      if (nB >= NE) nB = 0;
            sA = __ldg(&ei[nA]); dA = __ldg(&ei[NE + nA]);
            sB = __ldg(&ei[nB]); dB = __ldg(&ei[NE + nB]);
        }

        if (co == 0) {
            if (vA) { g_pseudo[ceA] = make_float4(ax, ay, az, 0.f); atomicAdd(&g_deg[cdA], 1.0f); }
            if (vB) { g_pseudo[ceB] = make_float4(bx, by, bz, 0.f); atomicAdd(&g_deg[cdB], 1.0f); }
        }

        float sumA = edge_comp(ax, ay, az, vA0, vA1, Px, Py, Pz, Pc);
        quad_red(sumA, co, vA, &aggr[(size_t)cdA * 16 + co]);
        float sumB = edge_comp(bx, by, bz, vB0, vB1, Px, Py, Pz, Pc);
        quad_red(sumB, co, vB, &aggr[(size_t)cdB * 16 + co]);
    }
}

// ---------------------------------------------------------------------------
// CI=16 edge kernel: full warp per edge, ci split across halves. Persistent,
// uniform ITER16 iterations (warp-uniform validity).
__global__ void __launch_bounds__(256, 4)
edge16_kernel(const float* __restrict__ hin,  // [NN, 16]
              const int*   __restrict__ ei,   // [2, NE]
              const float* __restrict__ lw, const float* __restrict__ lb,
              const float* __restrict__ ga, const float* __restrict__ be,
              float* __restrict__ aggr)       // [NN, 16]
{
    __shared__ ull sP[8 * 4 * 16];
    fold_smem((float*)sP, lw, lb, ga, be, 256);

    int lane = threadIdx.x & 31;
    int co = lane & 15, half = lane >> 4;

    ull Px[4], Py[4], Pz[4], Pc[4];
#pragma unroll
    for (int k = 0; k < 4; k++) {
        int kg = half * 4 + k;
        Px[k] = sP[(kg * 4 + 0) * 16 + co];
        Py[k] = sP[(kg * 4 + 1) * 16 + co];
        Pz[k] = sP[(kg * 4 + 2) * 16 + co];
        Pc[k] = sP[(kg * 4 + 3) * 16 + co];
    }

    int w = (blockIdx.x * 256 + threadIdx.x) >> 5;   // 0..NW16-1

    int eA = w, eB = w + NW16;
    int sA = __ldg(&ei[eA]), dA = __ldg(&ei[NE + eA]);
    int sB = __ldg(&ei[eB]), dB = __ldg(&ei[NE + eB]);
    float4 psA = __ldg(&g_pseudo[eA]);
    float4 psB = __ldg(&g_pseudo[eB]);

    for (int k = 0; k < ITER16; k++) {
        int ceA = w + k * 2 * NW16;
        int ceB = ceA + NW16;
        bool vA = (ceA < NE), vB = (ceB < NE);   // warp-uniform

        const ulonglong2* xrA = (const ulonglong2*)(hin + (size_t)sA * 16) + half * 2;
        const ulonglong2* xrB = (const ulonglong2*)(hin + (size_t)sB * 16) + half * 2;
        ulonglong2 vA0 = __ldg(&xrA[0]), vA1 = __ldg(&xrA[1]);
        ulonglong2 vB0 = __ldg(&xrB[0]), vB1 = __ldg(&xrB[1]);

        int cdA = dA, cdB = dB;
        float4 cpA = psA, cpB = psB;

        if (k + 1 < ITER16) {
            int nA = ceA + 2 * NW16; if (nA >= NE) nA = 0;
            int nB = nA + NW16;      if (nB >= NE) nB = 0;
            sA = __ldg(&ei[nA]); dA = __ldg(&ei[NE + nA]);
            sB = __ldg(&ei[nB]); dB = __ldg(&ei[NE + nB]);
            psA = __ldg(&g_pseudo[nA]);
            psB = __ldg(&g_pseudo[nB]);
        }

        {
            float sum = edge_comp(cpA.x, cpA.y, cpA.z, vA0, vA1, Px, Py, Pz, Pc);
            sum += __shfl_xor_sync(0xffffffffu, sum, 16);
            quad_red(sum, co, vA && lane < 16, &aggr[(size_t)cdA * 16 + co]);
        }
        {
            float sum = edge_comp(cpB.x, cpB.y, cpB.z, vB0, vB1, Px, Py, Pz, Pc);
            sum += __shfl_xor_sync(0xffffffffu, sum, 16);
            quad_red(sum, co, vB && lane < 16, &aggr[(size_t)cdB * 16 + co]);
        }
    }
}

// ---------------------------------------------------------------------------
// Node kernel: 4 threads per node (thread = co-quad). Re-zeroes aggr (+deg on last).
template<int CI, bool ZERODEG>
__global__ void __launch_bounds__(256)
node_kernel(const float* __restrict__ hin,
            const float* __restrict__ root,  // [CI, 16]
            const float* __restrict__ bias,  // [16]
            float* __restrict__ aggr,
            float* __restrict__ hout)        // [NN, 16]
{
    int i = blockIdx.x * blockDim.x + threadIdx.x;
    int n = i >> 2, q = i & 3;
    if (n >= NN) return;

    float inv = 1.0f / fmaxf(g_deg[n], 1.0f);
    if (ZERODEG && q == 0) g_deg[n] = 0.0f;

    float4* ar = (float4*)(aggr + (size_t)n * 16) + q;
    float4 a = *ar;
    float4 bi = __ldg((const float4*)bias + q);
    float acc0 = fmaf(a.x, inv, bi.x);
    float acc1 = fmaf(a.y, inv, bi.y);
    float acc2 = fmaf(a.z, inv, bi.z);
    float acc3 = fmaf(a.w, inv, bi.w);

#pragma unroll
    for (int ci = 0; ci < CI; ci++) {
        float xv = __ldg(&hin[(size_t)n * CI + ci]);
        float4 r = __ldg((const float4*)(root + ci * 16) + q);
        acc0 = fmaf(xv, r.x, acc0);
        acc1 = fmaf(xv, r.y, acc1);
        acc2 = fmaf(xv, r.z, acc2);
        acc3 = fmaf(xv, r.w, acc3);
    }

    float4 o;
    o.x = fmaxf(acc0, 0.0f);
    o.y = fmaxf(acc1, 0.0f);
    o.z = fmaxf(acc2, 0.0f);
    o.w = fmaxf(acc3, 0.0f);
    ((float4*)(hout + (size_t)n * 16))[q] = o;
    *ar = make_float4(0.f, 0.f, 0.f, 0.f);   // reset aggr for next layer / call
}

// ---------------------------------------------------------------------------
__global__ void gather_kernel(const float* __restrict__ h,
                              const float* __restrict__ pos,
                              const int*   __restrict__ batch,
                              const int*   __restrict__ idx,
                              float* __restrict__ out)
{
    int i = blockIdx.x * blockDim.x + threadIdx.x;
    if (i >= NIDX) return;
    int n = idx[i];
    float4* od = (float4*)(out + (size_t)i * 16);
    const float4* hs = (const float4*)(h + (size_t)n * 16);
#pragma unroll
    for (int q = 0; q < 4; q++) od[q] = hs[q];
    out[NIDX * 16 + i * 3 + 0] = pos[n * 3 + 0];
    out[NIDX * 16 + i * 3 + 1] = pos[n * 3 + 1];
    out[NIDX * 16 + i * 3 + 2] = pos[n * 3 + 2];
    reinterpret_cast<int*>(out)[NIDX * 19 + i] = batch[n];
}

// ---------------------------------------------------------------------------
extern "C" void kernel_launch(void* const* d_in, const int* in_sizes, int n_in,
                              void* d_out, int out_size)
{
    const float* x   = (const float*)d_in[0];
    const float* pos = (const float*)d_in[1];
    const float* lw0 = (const float*)d_in[2],  *lb0 = (const float*)d_in[3],
               * g0  = (const float*)d_in[4],  *be0 = (const float*)d_in[5],
               * r0  = (const float*)d_in[6],  *bi0 = (const float*)d_in[7];
    const float* lw1 = (const float*)d_in[8],  *lb1 = (const float*)d_in[9],
               * g1  = (const float*)d_in[10], *be1 = (const float*)d_in[11],
               * r1  = (const float*)d_in[12], *bi1 = (const float*)d_in[13];
    const float* lw2 = (const float*)d_in[14], *lb2 = (const float*)d_in[15],
               * g2  = (const float*)d_in[16], *be2 = (const float*)d_in[17],
               * r2  = (const float*)d_in[18], *bi2 = (const float*)d_in[19];
    const int* batch = (const int*)d_in[20];
    const int* idx   = (const int*)d_in[21];
    const int* ei    = (const int*)d_in[22];
    float* out = (float*)d_out;

    float *aggr, *h1, *h2;
    cudaGetSymbolAddress((void**)&aggr, g_aggr);
    cudaGetSymbolAddress((void**)&h1,   g_h1);
    cudaGetSymbolAddress((void**)&h2,   g_h2);

    dim3 node_grid((NN * 4 + 255) / 256);

    align_kernel<<<1, 32>>>();   // launch 0 (shifts ncu capture onto edge16)

    // Layer 0 (CI=8): x -> h1. Also computes pseudo + degree.
    edge8_kernel<<<EB, 256>>>(x, pos, ei, lw0, lb0, g0, be0, aggr);       // 1
    node_kernel<8, false><<<node_grid, 256>>>(x, r0, bi0, aggr, h1);      // 2

    // Layer 1 (CI=16): h1 -> h2
    edge16_kernel<<<EB, 256>>>(h1, ei, lw1, lb1, g1, be1, aggr);          // 3
    node_kernel<16, false><<<node_grid, 256>>>(h1, r1, bi1, aggr, h2);    // 4

    // Layer 2 (CI=16): h2 -> h1
    edge16_kernel<<<EB, 256>>>(h2, ei, lw2, lb2, g2, be2, aggr);          // 5 <- ncu
    node_kernel<16, true><<<node_grid, 256>>>(h2, r2, bi2, aggr, h1);     // 6

    gather_kernel<<<(NIDX + 255) / 256, 256>>>(h1, pos, batch, idx, out); // 7
}

// round 7
// speedup vs baseline: 1.0960x; 1.0708x over previous
#include <cuda_runtime.h>
#include <cuda_bf16.h>

#define NN 50000
#define NE 800000
#define NIDX 25000

#define EB 1250                     // edge-kernel blocks (R4-proven)
#define NSL8 20000                  // half-warp slots (edge8): 40 edges/slot exact
#define NW16 10000                  // warps (edge16): 80 edges/warp exact

typedef unsigned long long ull;

// Scratch (__device__ globals; zero-initialized at load).
// Invariants at START of every call: g_deg == 0, g_aggr == 0 (node kernels re-zero).
__device__ float g_deg [NN];
__device__ float g_aggr[NN * 16];
__device__ float g_h1  [NN * 16];
__device__ float g_h2  [NN * 16];
// Packed edge record, 32B/edge: {(px,px),(py,py),(pz,pz),(src|dst)} as 4 ull.
__device__ ull   g_epack[(size_t)NE * 4];
__device__ int   g_dummy;

// ---- packed f32x2 helpers -------------------------------------------------
__device__ __forceinline__ ull ffma2(ull a, ull b, ull c) {
    ull d;
    asm("fma.rn.f32x2 %0, %1, %2, %3;" : "=l"(d) : "l"(a), "l"(b), "l"(c));
    return d;
}
__device__ __forceinline__ ull pack2(float lo, float hi) {
    ull r;
    asm("mov.b64 %0, {%1, %2};" : "=l"(r) : "f"(lo), "f"(hi));
    return r;
}
__device__ __forceinline__ void unpack2(ull v, float& lo, float& hi) {
    asm("mov.b64 {%0, %1}, %2;" : "=f"(lo), "=f"(hi) : "l"(v));
}
__device__ __forceinline__ ull relu2(ull v) {
    float lo, hi;
    unpack2(v, lo, hi);
    lo = fmaxf(lo, 0.0f);
    hi = fmaxf(hi, 0.0f);
    return pack2(lo, hi);
}
__device__ __forceinline__ void red_v4(float* p, float a, float b, float c, float d) {
    asm volatile("red.global.add.v4.f32 [%0], {%1, %2, %3, %4};"
                 :: "l"(p), "f"(a), "f"(b), "f"(c), "f"(d) : "memory");
}

// Collect co-quads, one red.v4 per 4 lanes. ALL 32 lanes must reach this.
__device__ __forceinline__ void quad_red(float sum, int co, bool active, float* addr) {
    float b  = __shfl_xor_sync(0xffffffffu, sum, 1);
    float v0 = (co & 1) ? b : sum;
    float v1 = (co & 1) ? sum : b;
    float c0 = __shfl_xor_sync(0xffffffffu, v0, 2);
    float c1 = __shfl_xor_sync(0xffffffffu, v1, 2);
    if (active && (co & 3) == 0) red_v4(addr, v0, v1, c0, c1);
}

// Per-lane partial for one edge given PRE-PACKED pseudo pairs p0/p1/p2.
__device__ __forceinline__ float edge_comp_p(ull p0, ull p1, ull p2,
                                             ulonglong2 v0, ulonglong2 v1,
                                             const ull* Px, const ull* Py,
                                             const ull* Pz, const ull* Pc)
{
    ull xv[4] = { v0.x, v0.y, v1.x, v1.y };
    ull acc = 0;
#pragma unroll
    for (int q = 0; q < 4; q++) {
        ull w = ffma2(p2, Pz[q], Pc[q]);
        w = ffma2(p1, Py[q], w);
        w = ffma2(p0, Px[q], w);
        w = relu2(w);
        acc = ffma2(xv[q], w, acc);
    }
    float lo, hi;
    unpack2(acc, lo, hi);
    return lo + hi;
}

// Fold edge-MLP params into smem (packed over ci-pairs).
__device__ __forceinline__ void fold_smem(float* sf,
                                          const float* __restrict__ lw,
                                          const float* __restrict__ lb,
                                          const float* __restrict__ ga,
                                          const float* __restrict__ be, int D)
{
    for (int j = threadIdx.x; j < D; j += blockDim.x) {
        float g = ga[j];
        float c0 = lw[j] * g;
        float c1 = lw[D + j] * g;
        float c2 = lw[2 * D + j] * g;
        float c3 = fmaf(lb[j], g, be[j]);
        int ci = j >> 4, co = j & 15;
        int k = ci >> 1, h = ci & 1;
        sf[((k * 4 + 0) * 16 + co) * 2 + h] = c0;
        sf[((k * 4 + 1) * 16 + co) * 2 + h] = c1;
        sf[((k * 4 + 2) * 16 + co) * 2 + h] = c2;
        sf[((k * 4 + 3) * 16 + co) * 2 + h] = c3;
    }
    __syncthreads();
}

// Profiler-alignment no-op (puts 2nd edge16 at ncu capture slot 5).
__global__ void align_kernel() { if (threadIdx.x == 0) g_dummy = 0; }

// ---------------------------------------------------------------------------
// Layer-0 edge kernel (CI=8): half-warp per edge. Exact 40 edges/slot.
// Computes + stores the 32B packed edge record, degree, and layer-0 messages.
__global__ void __launch_bounds__(256)
edge8_kernel(const float* __restrict__ x,     // [NN, 8]
             const float* __restrict__ pos,   // [NN, 3]
             const int*   __restrict__ ei,    // [2, NE]
             const float* __restrict__ lw, const float* __restrict__ lb,
             const float* __restrict__ ga, const float* __restrict__ be,
             float* __restrict__ aggr)        // [NN, 16]
{
    __shared__ ull sP[4 * 4 * 16];
    fold_smem((float*)sP, lw, lb, ga, be, 128);

    int co = threadIdx.x & 15;
    ull Px[4], Py[4], Pz[4], Pc[4];
#pragma unroll
    for (int k = 0; k < 4; k++) {
        Px[k] = sP[(k * 4 + 0) * 16 + co];
        Py[k] = sP[(k * 4 + 1) * 16 + co];
        Pz[k] = sP[(k * 4 + 2) * 16 + co];
        Pc[k] = sP[(k * 4 + 3) * 16 + co];
    }

    int slot = (blockIdx.x * 256 + threadIdx.x) >> 4;   // 0..NSL8-1

    int eA = slot, eB = slot + NSL8;
    int sA = __ldg(&ei[eA]), dA = __ldg(&ei[NE + eA]);
    int sB = __ldg(&ei[eB]), dB = __ldg(&ei[NE + eB]);

    for (int k = 0; k < 40; k += 2) {
        float ax = __ldg(&pos[dA * 3 + 0]) - __ldg(&pos[sA * 3 + 0]);
        float ay = __ldg(&pos[dA * 3 + 1]) - __ldg(&pos[sA * 3 + 1]);
        float az = __ldg(&pos[dA * 3 + 2]) - __ldg(&pos[sA * 3 + 2]);
        float bx = __ldg(&pos[dB * 3 + 0]) - __ldg(&pos[sB * 3 + 0]);
        float by = __ldg(&pos[dB * 3 + 1]) - __ldg(&pos[sB * 3 + 1]);
        float bz = __ldg(&pos[dB * 3 + 2]) - __ldg(&pos[sB * 3 + 2]);
        const ulonglong2* xrA = (const ulonglong2*)(x + (size_t)sA * 8);
        const ulonglong2* xrB = (const ulonglong2*)(x + (size_t)sB * 8);
        ulonglong2 vA0 = __ldg(&xrA[0]), vA1 = __ldg(&xrA[1]);
        ulonglong2 vB0 = __ldg(&xrB[0]), vB1 = __ldg(&xrB[1]);

        int cdA = dA, cdB = dB, csA = sA, csB = sB;
        int ceA = eA, ceB = eB;

        if (k + 2 < 40) {
            eA += 2 * NSL8; eB += 2 * NSL8;
            sA = __ldg(&ei[eA]); dA = __ldg(&ei[NE + eA]);
            sB = __ldg(&ei[eB]); dB = __ldg(&ei[NE + eB]);
        }

        // Write packed edge records (2 lanes each) + degree.
        ull sdA = ((ull)(unsigned)cdA << 32) | (unsigned)csA;
        ull sdB = ((ull)(unsigned)cdB << 32) | (unsigned)csB;
        if (co == 0) {
            ulonglong2* pa = (ulonglong2*)&g_epack[(size_t)ceA * 4];
            pa[0] = make_ulonglong2(pack2(ax, ax), pack2(ay, ay));
            pa[1] = make_ulonglong2(pack2(az, az), sdA);
            atomicAdd(&g_deg[cdA], 1.0f);
        } else if (co == 1) {
            ulonglong2* pb = (ulonglong2*)&g_epack[(size_t)ceB * 4];
            pb[0] = make_ulonglong2(pack2(bx, bx), pack2(by, by));
            pb[1] = make_ulonglong2(pack2(bz, bz), sdB);
            atomicAdd(&g_deg[cdB], 1.0f);
        }

        float sumA = edge_comp_p(pack2(ax, ax), pack2(ay, ay), pack2(az, az),
                                 vA0, vA1, Px, Py, Pz, Pc);
        quad_red(sumA, co, true, &aggr[(size_t)cdA * 16 + co]);
        float sumB = edge_comp_p(pack2(bx, bx), pack2(by, by), pack2(bz, bz),
                                 vB0, vB1, Px, Py, Pz, Pc);
        quad_red(sumB, co, true, &aggr[(size_t)cdB * 16 + co]);
    }
}

// ---------------------------------------------------------------------------
// CI=16 edge kernel: full warp per edge, ci split across halves.
// Per edge: 2 uniform LDG.128 (packed record) + 2 LDG.128 (x row half).
__global__ void __launch_bounds__(256)
edge16_kernel(const float* __restrict__ hin,  // [NN, 16]
              const float* __restrict__ lw, const float* __restrict__ lb,
              const float* __restrict__ ga, const float* __restrict__ be,
              float* __restrict__ aggr)       // [NN, 16]
{
    __shared__ ull sP[8 * 4 * 16];
    fold_smem((float*)sP, lw, lb, ga, be, 256);

    int lane = threadIdx.x & 31;
    int co = lane & 15, half = lane >> 4;

    ull Px[4], Py[4], Pz[4], Pc[4];
#pragma unroll
    for (int k = 0; k < 4; k++) {
        int kg = half * 4 + k;
        Px[k] = sP[(kg * 4 + 0) * 16 + co];
        Py[k] = sP[(kg * 4 + 1) * 16 + co];
        Pz[k] = sP[(kg * 4 + 2) * 16 + co];
        Pc[k] = sP[(kg * 4 + 3) * 16 + co];
    }

    int w = (blockIdx.x * 256 + threadIdx.x) >> 5;   // 0..NW16-1

    // prefetch records for first pair
    const ulonglong2* rA = (const ulonglong2*)&g_epack[(size_t)w * 4];
    const ulonglong2* rB = (const ulonglong2*)&g_epack[(size_t)(w + NW16) * 4];
    ulonglong2 qA0 = __ldg(&rA[0]), qA1 = __ldg(&rA[1]);
    ulonglong2 qB0 = __ldg(&rB[0]), qB1 = __ldg(&rB[1]);

    for (int k = 0; k < 80; k += 2) {
        int sA = (int)(unsigned)(qA1.y & 0xffffffffu);
        int dA = (int)(unsigned)(qA1.y >> 32);
        int sB = (int)(unsigned)(qB1.y & 0xffffffffu);
        int dB = (int)(unsigned)(qB1.y >> 32);
        ull pA0 = qA0.x, pA1 = qA0.y, pA2 = qA1.x;
        ull pB0 = qB0.x, pB1 = qB0.y, pB2 = qB1.x;

        const ulonglong2* xrA = (const ulonglong2*)(hin + (size_t)sA * 16) + half * 2;
        const ulonglong2* xrB = (const ulonglong2*)(hin + (size_t)sB * 16) + half * 2;
        ulonglong2 vA0 = __ldg(&xrA[0]), vA1 = __ldg(&xrA[1]);
        ulonglong2 vB0 = __ldg(&xrB[0]), vB1 = __ldg(&xrB[1]);

        // prefetch next pair's records
        if (k + 2 < 80) {
            int nA = w + (k + 2) * NW16;
            const ulonglong2* nrA = (const ulonglong2*)&g_epack[(size_t)nA * 4];
            const ulonglong2* nrB = (const ulonglong2*)&g_epack[(size_t)(nA + NW16) * 4];
            qA0 = __ldg(&nrA[0]); qA1 = __ldg(&nrA[1]);
            qB0 = __ldg(&nrB[0]); qB1 = __ldg(&nrB[1]);
        }

        {
            float sum = edge_comp_p(pA0, pA1, pA2, vA0, vA1, Px, Py, Pz, Pc);
            sum += __shfl_xor_sync(0xffffffffu, sum, 16);
            quad_red(sum, co, lane < 16, &aggr[(size_t)dA * 16 + co]);
        }
        {
            float sum = edge_comp_p(pB0, pB1, pB2, vB0, vB1, Px, Py, Pz, Pc);
            sum += __shfl_xor_sync(0xffffffffu, sum, 16);
            quad_red(sum, co, lane < 16, &aggr[(size_t)dB * 16 + co]);
        }
    }
}

// ---------------------------------------------------------------------------
// Node kernel: 4 threads per node (thread = co-quad). Re-zeroes aggr (+deg on last).
template<int CI, bool ZERODEG>
__global__ void __launch_bounds__(256)
node_kernel(const float* __restrict__ hin,
            const float* __restrict__ root,  // [CI, 16]
            const float* __restrict__ bias,  // [16]
            float* __restrict__ aggr,
            float* __restrict__ hout)        // [NN, 16]
{
    int i = blockIdx.x * blockDim.x + threadIdx.x;
    int n = i >> 2, q = i & 3;
    if (n >= NN) return;

    float inv = 1.0f / fmaxf(g_deg[n], 1.0f);
    if (ZERODEG && q == 0) g_deg[n] = 0.0f;

    float4* ar = (float4*)(aggr + (size_t)n * 16) + q;
    float4 a = *ar;
    float4 bi = __ldg((const float4*)bias + q);
    float acc0 = fmaf(a.x, inv, bi.x);
    float acc1 = fmaf(a.y, inv, bi.y);
    float acc2 = fmaf(a.z, inv, bi.z);
    float acc3 = fmaf(a.w, inv, bi.w);

#pragma unroll
    for (int ci = 0; ci < CI; ci++) {
        float xv = __ldg(&hin[(size_t)n * CI + ci]);
        float4 r = __ldg((const float4*)(root + ci * 16) + q);
        acc0 = fmaf(xv, r.x, acc0);
        acc1 = fmaf(xv, r.y, acc1);
        acc2 = fmaf(xv, r.z, acc2);
        acc3 = fmaf(xv, r.w, acc3);
    }

    float4 o;
    o.x = fmaxf(acc0, 0.0f);
    o.y = fmaxf(acc1, 0.0f);
    o.z = fmaxf(acc2, 0.0f);
    o.w = fmaxf(acc3, 0.0f);
    ((float4*)(hout + (size_t)n * 16))[q] = o;
    *ar = make_float4(0.f, 0.f, 0.f, 0.f);   // reset aggr for next layer / call
}

// ---------------------------------------------------------------------------
__global__ void gather_kernel(const float* __restrict__ h,
                              const float* __restrict__ pos,
                              const int*   __restrict__ batch,
                              const int*   __restrict__ idx,
                              float* __restrict__ out)
{
    int i = blockIdx.x * blockDim.x + threadIdx.x;
    if (i >= NIDX) return;
    int n = idx[i];
    float4* od = (float4*)(out + (size_t)i * 16);
    const float4* hs = (const float4*)(h + (size_t)n * 16);
#pragma unroll
    for (int q = 0; q < 4; q++) od[q] = hs[q];
    out[NIDX * 16 + i * 3 + 0] = pos[n * 3 + 0];
    out[NIDX * 16 + i * 3 + 1] = pos[n * 3 + 1];
    out[NIDX * 16 + i * 3 + 2] = pos[n * 3 + 2];
    reinterpret_cast<int*>(out)[NIDX * 19 + i] = batch[n];
}

// ---------------------------------------------------------------------------
extern "C" void kernel_launch(void* const* d_in, const int* in_sizes, int n_in,
                              void* d_out, int out_size)
{
    const float* x   = (const float*)d_in[0];
    const float* pos = (const float*)d_in[1];
    const float* lw0 = (const float*)d_in[2],  *lb0 = (const float*)d_in[3],
               * g0  = (const float*)d_in[4],  *be0 = (const float*)d_in[5],
               * r0  = (const float*)d_in[6],  *bi0 = (const float*)d_in[7];
    const float* lw1 = (const float*)d_in[8],  *lb1 = (const float*)d_in[9],
               * g1  = (const float*)d_in[10], *be1 = (const float*)d_in[11],
               * r1  = (const float*)d_in[12], *bi1 = (const float*)d_in[13];
    const float* lw2 = (const float*)d_in[14], *lb2 = (const float*)d_in[15],
               * g2  = (const float*)d_in[16], *be2 = (const float*)d_in[17],
               * r2  = (const float*)d_in[18], *bi2 = (const float*)d_in[19];
    const int* batch = (const int*)d_in[20];
    const int* idx   = (const int*)d_in[21];
    const int* ei    = (const int*)d_in[22];
    float* out = (float*)d_out;

    float *aggr, *h1, *h2;
    cudaGetSymbolAddress((void**)&aggr, g_aggr);
    cudaGetSymbolAddress((void**)&h1,   g_h1);
    cudaGetSymbolAddress((void**)&h2,   g_h2);

    dim3 node_grid((NN * 4 + 255) / 256);

    align_kernel<<<1, 32>>>();                                            // 0

    // Layer 0 (CI=8): x -> h1. Also builds packed edge records + degree.
    edge8_kernel<<<EB, 256>>>(x, pos, ei, lw0, lb0, g0, be0, aggr);       // 1
    node_kernel<8, false><<<node_grid, 256>>>(x, r0, bi0, aggr, h1);      // 2

    // Layer 1 (CI=16): h1 -> h2
    edge16_kernel<<<EB, 256>>>(h1, lw1, lb1, g1, be1, aggr);              // 3
    node_kernel<16, false><<<node_grid, 256>>>(h1, r1, bi1, aggr, h2);    // 4

    // Layer 2 (CI=16): h2 -> h1
    edge16_kernel<<<EB, 256>>>(h2, lw2, lb2, g2, be2, aggr);              // 5 <- ncu
    node_kernel<16, true><<<node_grid, 256>>>(h2, r2, bi2, aggr, h1);     // 6

    gather_kernel<<<(NIDX + 255) / 256, 256>>>(h1, pos, batch, idx, out); // 7
}